// round 4
// baseline (speedup 1.0000x reference)
#include <cuda_runtime.h>
#include <math.h>

// ---------------------------------------------------------------------------
// ClusterAttn: b=1, D=32, H=128, W=128, C=96, P=4, FEAD=64, K=64
// Pipeline:
//  k1  : dwc stage1  y_t[p] = dot_c(x[p,:], w[:,t])   (27 maps, f32x2 FMA)
//  k2  : dwc stage2  dnx gather + pool to fea tokens + colwise sum-of-squares
//  k3  : inv column norms
//  k4a : normalize fea in place
//  k4b : logits = fea @ centroids^T, exp
//  k4c : per-cluster column sums (softmax-over-N denominator)
//  k5  : M = E^T @ fea  -> new_centroids = M / colsum
//  k6  : kv = newc @ kv_w^T + kv_b -> k_, v_
//  k7a : q = fea @ q_w^T + q_b
//  k7b1: attn logits = q @ k^T / 8
//  k7b2: row softmax
//  k7c : out = attn @ v
//  k8  : scatter tokens back to 1-channel volume o1
//  k9  : upc conv (1->96) + bias + residual x, channel-pair f32x2
// ---------------------------------------------------------------------------

#define DD 32
#define HH 128
#define WW 128
#define NP (DD*HH*WW)      // 524288 voxels
#define CC 96
#define NT 8192            // tokens
#define FE 64              // FEAD
#define KK 64              // clusters

// ------------------------- scratch (device globals) -------------------------
__device__ __align__(256) float g_y[27*NP];        // 56.6 MB
__device__ __align__(256) float g_fea[NT*FE];
__device__ __align__(256) float g_expl[NT*KK];
__device__ __align__(256) float g_q[NT*FE];
__device__ __align__(256) float g_attn[NT*KK];
__device__ __align__(256) float g_out[NT*FE];
__device__ __align__(256) float g_o1[NP];
__device__ __align__(256) float g_ssq[FE];
__device__ __align__(256) float g_inv[FE];
__device__ __align__(256) float g_colsum[KK];
__device__ __align__(256) float g_newc[KK*FE];
__device__ __align__(256) float g_k[KK*FE];
__device__ __align__(256) float g_v[KK*FE];

// ------------------------- f32x2 packed helpers -----------------------------
using u64 = unsigned long long;
__device__ __forceinline__ u64 pk2(float a, float b) {
    u64 r; asm("mov.b64 %0,{%1,%2};" : "=l"(r) : "f"(a), "f"(b)); return r;
}
__device__ __forceinline__ float2 upk2(u64 v) {
    float2 r; asm("mov.b64 {%0,%1},%2;" : "=f"(r.x), "=f"(r.y) : "l"(v)); return r;
}
__device__ __forceinline__ u64 ffma2(u64 a, u64 b, u64 c) {
    u64 d; asm("fma.rn.f32x2 %0,%1,%2,%3;" : "=l"(d) : "l"(a), "l"(b), "l"(c)); return d;
}

// ------------------------- k0: init small accumulators ----------------------
__global__ void k0_init() {
    int t = threadIdx.x;
    if (t < FE) g_ssq[t] = 0.f;
}

// ------------------------- k1: dwc stage1 -----------------------------------
// Each thread: 2 consecutive voxels packed in f32x2. y[t][p] = sum_c x[p,c]*w[c,t]
__global__ __launch_bounds__(256) void k1_dwc1(const float* __restrict__ x,
                                               const float* __restrict__ dwc_w) {
    __shared__ u64 w2[CC*27];
    for (int i = threadIdx.x; i < CC*27; i += 256) { float v = dwc_w[i]; w2[i] = pk2(v, v); }
    __syncthreads();

    int pr = blockIdx.x*256 + threadIdx.x;       // voxel pair id, 0..NP/2-1
    const float* xa = x + (size_t)pr * 192;      // 2 voxels * 96 ch

    u64 acc[27];
#pragma unroll
    for (int t = 0; t < 27; t++) acc[t] = 0ull;

    for (int c = 0; c < CC; c += 4) {
        float4 a4 = *reinterpret_cast<const float4*>(xa + c);
        float4 b4 = *reinterpret_cast<const float4*>(xa + 96 + c);
        u64 p0 = pk2(a4.x, b4.x), p1 = pk2(a4.y, b4.y);
        u64 p2 = pk2(a4.z, b4.z), p3 = pk2(a4.w, b4.w);
        const u64* wc = w2 + c*27;
#pragma unroll
        for (int t = 0; t < 27; t++) {
            acc[t] = ffma2(p0, wc[t],      acc[t]);
            acc[t] = ffma2(p1, wc[27+t],   acc[t]);
            acc[t] = ffma2(p2, wc[54+t],   acc[t]);
            acc[t] = ffma2(p3, wc[81+t],   acc[t]);
        }
    }
#pragma unroll
    for (int t = 0; t < 27; t++) {
        float2 v = upk2(acc[t]);
        *reinterpret_cast<float2*>(g_y + (size_t)t*NP + pr*2) = v;
    }
}

// ------------------------- k2: gather + pool to fea + ssq -------------------
__global__ __launch_bounds__(256) void k2_gather(const float* __restrict__ dwc_b) {
    __shared__ float ssq_s[FE];
    if (threadIdx.x < FE) ssq_s[threadIdx.x] = 0.f;
    __syncthreads();

    int idx = blockIdx.x*256 + threadIdx.x;      // == n*64 + f  (NP total)
    int n = idx >> 6, f = idx & 63;
    int xb = n & 31, yb = (n >> 5) & 31, zb = n >> 10;
    int px = f & 3, py = (f >> 2) & 3, pz = f >> 4;
    int z = zb*4 + pz, y = yb*4 + py, xx = xb*4 + px;

    float v = dwc_b[0];
#pragma unroll
    for (int kz = 0; kz < 3; kz++) {
        int zz = z + kz - 1; if ((unsigned)zz >= DD) continue;
#pragma unroll
        for (int ky = 0; ky < 3; ky++) {
            int yy = y + ky - 1; if ((unsigned)yy >= HH) continue;
#pragma unroll
            for (int kx = 0; kx < 3; kx++) {
                int xc = xx + kx - 1; if ((unsigned)xc >= WW) continue;
                int t = kz*9 + ky*3 + kx;
                v += g_y[(size_t)t*NP + (zz*HH + yy)*WW + xc];
            }
        }
    }
    g_fea[idx] = v;
    atomicAdd(&ssq_s[f], v*v);
    __syncthreads();
    if (threadIdx.x < FE) atomicAdd(&g_ssq[threadIdx.x], ssq_s[threadIdx.x]);
}

// ------------------------- k3: inverse column norms -------------------------
__global__ void k3_inv() {
    int f = threadIdx.x;
    if (f < FE) g_inv[f] = 1.f / fmaxf(sqrtf(g_ssq[f]), 1e-12f);
}

// ------------------------- k4a: normalize fea in place ----------------------
__global__ void k4a_norm() {
    int i = blockIdx.x*256 + threadIdx.x;        // float4 index, NT*FE/4 total
    float4* p = reinterpret_cast<float4*>(g_fea);
    float4 v = p[i];
    int f0 = (i*4) & 63;
    v.x *= g_inv[f0]; v.y *= g_inv[f0+1]; v.z *= g_inv[f0+2]; v.w *= g_inv[f0+3];
    p[i] = v;
}

// ------------------------- k4b: logits + exp --------------------------------
__global__ __launch_bounds__(256) void k4b_logits(const float* __restrict__ cen) {
    __shared__ float4 cen_s[KK*16];
    for (int i = threadIdx.x; i < KK*16; i += 256)
        cen_s[i] = reinterpret_cast<const float4*>(cen)[i];
    __syncthreads();

    int idx = blockIdx.x*256 + threadIdx.x;      // 32768: (n, c-quarter)
    int n = idx >> 2, c0 = (idx & 3) * 16;
    float fr[FE];
    const float4* frp = reinterpret_cast<const float4*>(g_fea + n*FE);
#pragma unroll
    for (int f4 = 0; f4 < 16; f4++) {
        float4 v = frp[f4];
        fr[f4*4] = v.x; fr[f4*4+1] = v.y; fr[f4*4+2] = v.z; fr[f4*4+3] = v.w;
    }
#pragma unroll
    for (int cc = 0; cc < 16; cc++) {
        int c = c0 + cc;
        const float4* cr = cen_s + c*16;
        float l = 0.f;
#pragma unroll
        for (int f4 = 0; f4 < 16; f4++) {
            float4 w = cr[f4];
            l += fr[f4*4]*w.x + fr[f4*4+1]*w.y + fr[f4*4+2]*w.z + fr[f4*4+3]*w.w;
        }
        g_expl[n*KK + c] = __expf(l);
    }
}

// ------------------------- k4c: per-cluster column sums ---------------------
__global__ void k4c_colsum() {                   // grid 64, block 256
    int c = blockIdx.x;
    float s = 0.f;
    for (int n = threadIdx.x; n < NT; n += 256) s += g_expl[n*KK + c];
    __shared__ float sm[8];
    int lane = threadIdx.x & 31, w = threadIdx.x >> 5;
#pragma unroll
    for (int o = 16; o > 0; o >>= 1) s += __shfl_down_sync(0xffffffffu, s, o);
    if (lane == 0) sm[w] = s;
    __syncthreads();
    if (threadIdx.x == 0) {
        float t = 0.f;
#pragma unroll
        for (int i = 0; i < 8; i++) t += sm[i];
        g_colsum[c] = t;
    }
}

// ------------------------- k5: new_centroids = (E^T @ fea)/colsum -----------
__global__ __launch_bounds__(256) void k5_newc() {   // grid 64 (cluster c)
    int c = blockIdx.x;
    float acc[FE];
#pragma unroll
    for (int f = 0; f < FE; f++) acc[f] = 0.f;
    for (int n = threadIdx.x; n < NT; n += 256) {
        float e = g_expl[n*KK + c];
        const float4* fr = reinterpret_cast<const float4*>(g_fea + n*FE);
#pragma unroll
        for (int f4 = 0; f4 < 16; f4++) {
            float4 v = fr[f4];
            acc[f4*4]   += e*v.x; acc[f4*4+1] += e*v.y;
            acc[f4*4+2] += e*v.z; acc[f4*4+3] += e*v.w;
        }
    }
    __shared__ float red[FE];
    if (threadIdx.x < FE) red[threadIdx.x] = 0.f;
    __syncthreads();
    int lane = threadIdx.x & 31;
#pragma unroll
    for (int f = 0; f < FE; f++) {
        float r = acc[f];
#pragma unroll
        for (int o = 16; o > 0; o >>= 1) r += __shfl_down_sync(0xffffffffu, r, o);
        if (lane == 0) atomicAdd(&red[f], r);
    }
    __syncthreads();
    if (threadIdx.x < FE)
        g_newc[c*FE + threadIdx.x] = red[threadIdx.x] / g_colsum[c];
}

// ------------------------- k6: kv projection --------------------------------
__global__ void k6_kv(const float* __restrict__ kv_w, const float* __restrict__ kv_b) {
    __shared__ float nc_s[FE];                   // grid 64 (c), block 128 (j)
    int c = blockIdx.x, j = threadIdx.x;
    if (j < FE) nc_s[j] = g_newc[c*FE + j];
    __syncthreads();
    float acc = kv_b[j];
    const float* wr = kv_w + j*FE;
#pragma unroll
    for (int f = 0; f < FE; f++) acc += nc_s[f] * wr[f];
    if (j < 64) g_k[c*FE + j] = acc;
    else        g_v[c*FE + (j - 64)] = acc;
}

// ------------------------- k7a: q projection --------------------------------
__global__ __launch_bounds__(256) void k7a_q(const float* __restrict__ qw,
                                             const float* __restrict__ qb) {
    __shared__ float4 qw_s[FE*16];
    __shared__ float qb_s[FE];
    for (int i = threadIdx.x; i < FE*16; i += 256)
        qw_s[i] = reinterpret_cast<const float4*>(qw)[i];
    if (threadIdx.x < FE) qb_s[threadIdx.x] = qb[threadIdx.x];
    __syncthreads();

    int idx = blockIdx.x*256 + threadIdx.x;
    int n = idx >> 2, j0 = (idx & 3) * 16;
    float fr[FE];
    const float4* frp = reinterpret_cast<const float4*>(g_fea + n*FE);
#pragma unroll
    for (int f4 = 0; f4 < 16; f4++) {
        float4 v = frp[f4];
        fr[f4*4] = v.x; fr[f4*4+1] = v.y; fr[f4*4+2] = v.z; fr[f4*4+3] = v.w;
    }
    for (int jj = 0; jj < 16; jj++) {
        int j = j0 + jj;
        float acc = qb_s[j];
        const float4* wr = qw_s + j*16;
#pragma unroll
        for (int f4 = 0; f4 < 16; f4++) {
            float4 w = wr[f4];
            acc += fr[f4*4]*w.x + fr[f4*4+1]*w.y + fr[f4*4+2]*w.z + fr[f4*4+3]*w.w;
        }
        g_q[n*FE + j] = acc;
    }
}

// ------------------------- k7b1: attention logits ---------------------------
__global__ __launch_bounds__(256) void k7b1_al() {
    __shared__ float4 k_s[KK*16];
    for (int i = threadIdx.x; i < KK*16; i += 256)
        k_s[i] = reinterpret_cast<const float4*>(g_k)[i];
    __syncthreads();

    int idx = blockIdx.x*256 + threadIdx.x;
    int n = idx >> 2, c0 = (idx & 3) * 16;
    float qr[FE];
    const float4* qp = reinterpret_cast<const float4*>(g_q + n*FE);
#pragma unroll
    for (int f4 = 0; f4 < 16; f4++) {
        float4 v = qp[f4];
        qr[f4*4] = v.x; qr[f4*4+1] = v.y; qr[f4*4+2] = v.z; qr[f4*4+3] = v.w;
    }
    for (int cc = 0; cc < 16; cc++) {
        int c = c0 + cc;
        const float4* kr = k_s + c*16;
        float l = 0.f;
#pragma unroll
        for (int f4 = 0; f4 < 16; f4++) {
            float4 w = kr[f4];
            l += qr[f4*4]*w.x + qr[f4*4+1]*w.y + qr[f4*4+2]*w.z + qr[f4*4+3]*w.w;
        }
        g_attn[n*KK + c] = l * 0.125f;
    }
}

// ------------------------- k7b2: row softmax --------------------------------
__global__ void k7b2_sm() {                      // grid 32, block 256
    int n = blockIdx.x*256 + threadIdx.x;
    float a[KK];
    float4* ap = reinterpret_cast<float4*>(g_attn + n*KK);
    float m = -1e30f;
#pragma unroll
    for (int i = 0; i < 16; i++) {
        float4 v = ap[i];
        a[i*4] = v.x; a[i*4+1] = v.y; a[i*4+2] = v.z; a[i*4+3] = v.w;
        m = fmaxf(m, fmaxf(fmaxf(v.x, v.y), fmaxf(v.z, v.w)));
    }
    float s = 0.f;
#pragma unroll
    for (int c = 0; c < KK; c++) { a[c] = __expf(a[c] - m); s += a[c]; }
    float si = 1.f / s;
#pragma unroll
    for (int i = 0; i < 16; i++)
        ap[i] = make_float4(a[i*4]*si, a[i*4+1]*si, a[i*4+2]*si, a[i*4+3]*si);
}

// ------------------------- k7c: out = attn @ v ------------------------------
__global__ __launch_bounds__(256) void k7c_out() {
    __shared__ float4 v_s[KK*16];
    for (int i = threadIdx.x; i < KK*16; i += 256)
        v_s[i] = reinterpret_cast<const float4*>(g_v)[i];
    __syncthreads();

    int idx = blockIdx.x*256 + threadIdx.x;
    int n = idx >> 2, f0 = (idx & 3) * 16;
    float a[KK];
    const float4* ap = reinterpret_cast<const float4*>(g_attn + n*KK);
#pragma unroll
    for (int i = 0; i < 16; i++) {
        float4 v = ap[i];
        a[i*4] = v.x; a[i*4+1] = v.y; a[i*4+2] = v.z; a[i*4+3] = v.w;
    }
    float acc[16];
#pragma unroll
    for (int k = 0; k < 16; k++) acc[k] = 0.f;
    for (int c = 0; c < KK; c++) {
        float ac = a[c];
        const float4* vr = v_s + c*16 + (f0 >> 2);
#pragma unroll
        for (int k = 0; k < 4; k++) {
            float4 v = vr[k];
            acc[k*4]   += ac*v.x; acc[k*4+1] += ac*v.y;
            acc[k*4+2] += ac*v.z; acc[k*4+3] += ac*v.w;
        }
    }
    float4* op = reinterpret_cast<float4*>(g_out + n*FE + f0);
#pragma unroll
    for (int k = 0; k < 4; k++)
        op[k] = make_float4(acc[k*4], acc[k*4+1], acc[k*4+2], acc[k*4+3]);
}

// ------------------------- k8: scatter tokens to volume ---------------------
__global__ void k8_scatter() {
    int idx = blockIdx.x*256 + threadIdx.x;
    int n = idx >> 6, f = idx & 63;
    int xb = n & 31, yb = (n >> 5) & 31, zb = n >> 10;
    int px = f & 3, py = (f >> 2) & 3, pz = f >> 4;
    int p = ((zb*4 + pz)*HH + (yb*4 + py))*WW + (xb*4 + px);
    g_o1[p] = g_out[idx];
}

// ------------------------- k9: upc conv + bias + residual -------------------
__global__ __launch_bounds__(256) void k9_upc(const float* __restrict__ x,
                                              const float* __restrict__ uw,
                                              const float* __restrict__ ub,
                                              float* __restrict__ out) {
    __shared__ u64 w2[48*27];
    __shared__ float2 b2[48];
    for (int i = threadIdx.x; i < 48*27; i += 256) {
        int cp = i / 27, t = i % 27;
        w2[i] = pk2(uw[(2*cp)*27 + t], uw[(2*cp + 1)*27 + t]);
    }
    if (threadIdx.x < 48)
        b2[threadIdx.x] = make_float2(ub[2*threadIdx.x], ub[2*threadIdx.x + 1]);
    __syncthreads();

    int p = blockIdx.x*256 + threadIdx.x;
    int z = p >> 14, y = (p >> 7) & 127, xx = p & 127;

    u64 o2[27];
#pragma unroll
    for (int kz = 0; kz < 3; kz++)
#pragma unroll
    for (int ky = 0; ky < 3; ky++)
#pragma unroll
    for (int kx = 0; kx < 3; kx++) {
        int zz = z + kz - 1, yy = y + ky - 1, xc = xx + kx - 1;
        float v = 0.f;
        if ((unsigned)zz < DD && (unsigned)yy < HH && (unsigned)xc < WW)
            v = g_o1[(zz*HH + yy)*WW + xc];
        o2[kz*9 + ky*3 + kx] = pk2(v, v);
    }

    const float2* xr = reinterpret_cast<const float2*>(x + (size_t)p*CC);
    float2* orow = reinterpret_cast<float2*>(out + (size_t)p*CC);
    for (int cp = 0; cp < 48; cp++) {
        float2 xv = xr[cp];
        float2 bb = b2[cp];
        u64 acc = pk2(xv.x + bb.x, xv.y + bb.y);
        const u64* wr = w2 + cp*27;
#pragma unroll
        for (int t = 0; t < 27; t++) acc = ffma2(o2[t], wr[t], acc);
        float2 r = upk2(acc);
        orow[cp] = r;
    }
}

// ------------------------- launch --------------------------------------------
extern "C" void kernel_launch(void* const* d_in, const int* in_sizes, int n_in,
                              void* d_out, int out_size) {
    const float* x     = (const float*)d_in[0];
    const float* cen   = (const float*)d_in[1];
    const float* dwc_w = (const float*)d_in[2];
    const float* dwc_b = (const float*)d_in[3];
    const float* upc_w = (const float*)d_in[4];
    const float* upc_b = (const float*)d_in[5];
    const float* q_w   = (const float*)d_in[6];
    const float* q_b   = (const float*)d_in[7];
    const float* kv_w  = (const float*)d_in[8];
    const float* kv_b  = (const float*)d_in[9];
    float* out = (float*)d_out;

    k0_init   <<<1, 64>>>();
    k1_dwc1   <<<NP/2/256, 256>>>(x, dwc_w);
    k2_gather <<<NP/256,   256>>>(dwc_b);
    k3_inv    <<<1, 64>>>();
    k4a_norm  <<<(NT*FE/4)/256, 256>>>();
    k4b_logits<<<(NT*4)/256, 256>>>(cen);
    k4c_colsum<<<KK, 256>>>();
    k5_newc   <<<KK, 256>>>();
    k6_kv     <<<KK, 128>>>(kv_w, kv_b);
    k7a_q     <<<(NT*4)/256, 256>>>(q_w, q_b);
    k7b1_al   <<<(NT*4)/256, 256>>>();
    k7b2_sm   <<<NT/256, 256>>>();
    k7c_out   <<<(NT*4)/256, 256>>>();
    k8_scatter<<<NP/256, 256>>>();
    k9_upc    <<<NP/256, 256>>>(x, upc_w, upc_b, out);
}

// round 5
// speedup vs baseline: 1.4989x; 1.4989x over previous
#include <cuda_runtime.h>
#include <math.h>

// ---------------------------------------------------------------------------
// ClusterAttn: b=1, D=32, H=128, W=128, C=96, P=4, FEAD=64, K=64
// ---------------------------------------------------------------------------

#define DD 32
#define HH 128
#define WW 128
#define NP (DD*HH*WW)      // 524288 voxels
#define CC 96
#define NT 8192            // tokens
#define FE 64              // FEAD
#define KK 64              // clusters

// ------------------------- scratch (device globals) -------------------------
__device__ __align__(256) float g_y[27*NP];        // 56.6 MB
__device__ __align__(256) float g_fea[NT*FE];
__device__ __align__(256) float g_expl[NT*KK];
__device__ __align__(256) float g_q[NT*FE];
__device__ __align__(256) float g_attn[NT*KK];
__device__ __align__(256) float g_out[NT*FE];
__device__ __align__(256) float g_o1[NP];
__device__ __align__(256) float g_ssq[FE];
__device__ __align__(256) float g_inv[FE];
__device__ __align__(256) float g_colsum[KK];
__device__ __align__(256) float g_newc[KK*FE];
__device__ __align__(256) float g_k[KK*FE];
__device__ __align__(256) float g_v[KK*FE];

// ------------------------- f32x2 packed helpers -----------------------------
using u64 = unsigned long long;
__device__ __forceinline__ u64 pk2(float a, float b) {
    u64 r; asm("mov.b64 %0,{%1,%2};" : "=l"(r) : "f"(a), "f"(b)); return r;
}
__device__ __forceinline__ float2 upk2(u64 v) {
    float2 r; asm("mov.b64 {%0,%1},%2;" : "=f"(r.x), "=f"(r.y) : "l"(v)); return r;
}
__device__ __forceinline__ u64 ffma2(u64 a, u64 b, u64 c) {
    u64 d; asm("fma.rn.f32x2 %0,%1,%2,%3;" : "=l"(d) : "l"(a), "l"(b), "l"(c)); return d;
}

// ------------------------- k0: init accumulators ----------------------------
__global__ void k0_init() {
    int t = threadIdx.x;
    if (t < FE) g_ssq[t] = 0.f;
}

// ------------------------- k1: dwc stage1  Y[NP,27] = X[NP,96] @ W[96,27] ----
// Block 128 threads / 512 voxels. x staged via shared (coalesced), 4 voxels
// per thread so each broadcast weight LDS feeds 2 FFMA2.
#define K1_NV 512
__global__ __launch_bounds__(128) void k1_dwc1(const float* __restrict__ x,
                                               const float* __restrict__ dwc_w) {
    __shared__ u64   w2[CC*27];          // (w,w) pairs
    __shared__ float xs[8][K1_NV + 4];
    int tid = threadIdx.x;
    for (int i = tid; i < CC*27; i += 128) { float v = dwc_w[i]; w2[i] = pk2(v, v); }

    int vbase = blockIdx.x * K1_NV;
    u64 acc0[27], acc1[27];
#pragma unroll
    for (int t = 0; t < 27; t++) { acc0[t] = 0ull; acc1[t] = 0ull; }

    for (int cb = 0; cb < CC; cb += 8) {
        __syncthreads();
#pragma unroll
        for (int it = 0; it < 8; it++) {       // stage 512 vox x 8 ch, coalesced
            int e = it*128 + tid;
            int v = e >> 1, slot = e & 1;
            float4 val = *reinterpret_cast<const float4*>(
                x + (size_t)(vbase + v)*CC + cb + slot*4);
            xs[slot*4+0][v] = val.x;
            xs[slot*4+1][v] = val.y;
            xs[slot*4+2][v] = val.z;
            xs[slot*4+3][v] = val.w;
        }
        __syncthreads();
        int vq = tid*4;
#pragma unroll
        for (int cq = 0; cq < 2; cq++) {
            u64 p[4], r[4];
#pragma unroll
            for (int j = 0; j < 4; j++) {
                float4 xv = *reinterpret_cast<const float4*>(&xs[cq*4+j][vq]);
                p[j] = pk2(xv.x, xv.y);
                r[j] = pk2(xv.z, xv.w);
            }
            const u64* wc = w2 + (cb + cq*4)*27;
#pragma unroll
            for (int t = 0; t < 27; t++) {
                u64 wa = wc[t], wb = wc[27+t], wv = wc[54+t], wd = wc[81+t];
                acc0[t] = ffma2(p[0], wa, acc0[t]); acc1[t] = ffma2(r[0], wa, acc1[t]);
                acc0[t] = ffma2(p[1], wb, acc0[t]); acc1[t] = ffma2(r[1], wb, acc1[t]);
                acc0[t] = ffma2(p[2], wv, acc0[t]); acc1[t] = ffma2(r[2], wv, acc1[t]);
                acc0[t] = ffma2(p[3], wd, acc0[t]); acc1[t] = ffma2(r[3], wd, acc1[t]);
            }
        }
    }
    int gq = vbase + tid*4;
#pragma unroll
    for (int t = 0; t < 27; t++) {
        float2 a = upk2(acc0[t]), b = upk2(acc1[t]);
        *reinterpret_cast<float4*>(g_y + (size_t)t*NP + gq) =
            make_float4(a.x, a.y, b.x, b.y);
    }
}

// ------------------------- k2: gather + fea + ssq (voxel-major) -------------
__global__ __launch_bounds__(256) void k2_gather(const float* __restrict__ dwc_b) {
    __shared__ float ssq_s[FE];
    int tid = threadIdx.x;
    if (tid < FE) ssq_s[tid] = 0.f;
    __syncthreads();

    int p = blockIdx.x*256 + tid;
    int z = p >> 14, y = (p >> 7) & 127, xx = p & 127;

    float v = dwc_b[0];
#pragma unroll
    for (int kz = 0; kz < 3; kz++) {
        int zz = z + kz - 1; if ((unsigned)zz >= DD) continue;
#pragma unroll
        for (int ky = 0; ky < 3; ky++) {
            int yy = y + ky - 1; if ((unsigned)yy >= HH) continue;
#pragma unroll
            for (int kx = 0; kx < 3; kx++) {
                int xc = xx + kx - 1; if ((unsigned)xc >= WW) continue;
                int t = kz*9 + ky*3 + kx;
                v += g_y[(size_t)t*NP + (zz*HH + yy)*WW + xc];
            }
        }
    }
    int n = ((z >> 2) << 10) | ((y >> 2) << 5) | (xx >> 2);
    int f = ((z & 3) << 4) | ((y & 3) << 2) | (xx & 3);
    g_fea[n*FE + f] = v;
    atomicAdd(&ssq_s[f], v*v);
    __syncthreads();
    if (tid < FE) atomicAdd(&g_ssq[tid], ssq_s[tid]);
}

// ------------------------- k3: inverse column norms -------------------------
__global__ void k3_inv() {
    int f = threadIdx.x;
    if (f < FE) g_inv[f] = 1.f / fmaxf(sqrtf(g_ssq[f]), 1e-12f);
}

// ------------------------- k4a: normalize fea in place ----------------------
__global__ void k4a_norm() {
    int i = blockIdx.x*256 + threadIdx.x;        // float4 index, NT*FE/4 total
    float4* p = reinterpret_cast<float4*>(g_fea);
    float4 v = p[i];
    int f0 = (i*4) & 63;
    v.x *= g_inv[f0]; v.y *= g_inv[f0+1]; v.z *= g_inv[f0+2]; v.w *= g_inv[f0+3];
    p[i] = v;
}

// ------------------------- k4b: logits + exp --------------------------------
__global__ __launch_bounds__(256) void k4b_logits(const float* __restrict__ cen) {
    __shared__ float4 cen_s[KK*16];
    for (int i = threadIdx.x; i < KK*16; i += 256)
        cen_s[i] = reinterpret_cast<const float4*>(cen)[i];
    __syncthreads();

    int idx = blockIdx.x*256 + threadIdx.x;      // (n, c-quarter)
    int n = idx >> 2, c0 = (idx & 3) * 16;
    float fr[FE];
    const float4* frp = reinterpret_cast<const float4*>(g_fea + n*FE);
#pragma unroll
    for (int f4 = 0; f4 < 16; f4++) {
        float4 v = frp[f4];
        fr[f4*4] = v.x; fr[f4*4+1] = v.y; fr[f4*4+2] = v.z; fr[f4*4+3] = v.w;
    }
#pragma unroll
    for (int cc = 0; cc < 16; cc++) {
        int c = c0 + cc;
        const float4* cr = cen_s + c*16;
        float l = 0.f;
#pragma unroll
        for (int f4 = 0; f4 < 16; f4++) {
            float4 w = cr[f4];
            l += fr[f4*4]*w.x + fr[f4*4+1]*w.y + fr[f4*4+2]*w.z + fr[f4*4+3]*w.w;
        }
        g_expl[n*KK + c] = __expf(l);
    }
}

// ------------------------- k4c: per-cluster column sums ---------------------
__global__ void k4c_colsum() {                   // grid 64, block 256
    int c = blockIdx.x;
    float s = 0.f;
    for (int n = threadIdx.x; n < NT; n += 256) s += g_expl[n*KK + c];
    __shared__ float sm[8];
    int lane = threadIdx.x & 31, w = threadIdx.x >> 5;
#pragma unroll
    for (int o = 16; o > 0; o >>= 1) s += __shfl_down_sync(0xffffffffu, s, o);
    if (lane == 0) sm[w] = s;
    __syncthreads();
    if (threadIdx.x == 0) {
        float t = 0.f;
#pragma unroll
        for (int i = 0; i < 8; i++) t += sm[i];
        g_colsum[c] = t;
    }
}

// ------------------------- k5: new_centroids = (E^T @ fea)/colsum -----------
__global__ __launch_bounds__(256) void k5_newc() {   // grid 64 (cluster c)
    int c = blockIdx.x;
    float acc[FE];
#pragma unroll
    for (int f = 0; f < FE; f++) acc[f] = 0.f;
    for (int n = threadIdx.x; n < NT; n += 256) {
        float e = g_expl[n*KK + c];
        const float4* fr = reinterpret_cast<const float4*>(g_fea + n*FE);
#pragma unroll
        for (int f4 = 0; f4 < 16; f4++) {
            float4 v = fr[f4];
            acc[f4*4]   += e*v.x; acc[f4*4+1] += e*v.y;
            acc[f4*4+2] += e*v.z; acc[f4*4+3] += e*v.w;
        }
    }
    __shared__ float red[FE];
    if (threadIdx.x < FE) red[threadIdx.x] = 0.f;
    __syncthreads();
    int lane = threadIdx.x & 31;
#pragma unroll
    for (int f = 0; f < FE; f++) {
        float r = acc[f];
#pragma unroll
        for (int o = 16; o > 0; o >>= 1) r += __shfl_down_sync(0xffffffffu, r, o);
        if (lane == 0) atomicAdd(&red[f], r);
    }
    __syncthreads();
    if (threadIdx.x < FE)
        g_newc[c*FE + threadIdx.x] = red[threadIdx.x] / g_colsum[c];
}

// ------------------------- k6: kv projection --------------------------------
__global__ void k6_kv(const float* __restrict__ kv_w, const float* __restrict__ kv_b) {
    __shared__ float nc_s[FE];                   // grid 64 (c), block 128 (j)
    int c = blockIdx.x, j = threadIdx.x;
    if (j < FE) nc_s[j] = g_newc[c*FE + j];
    __syncthreads();
    float acc = kv_b[j];
    const float* wr = kv_w + j*FE;
#pragma unroll
    for (int f = 0; f < FE; f++) acc += nc_s[f] * wr[f];
    if (j < 64) g_k[c*FE + j] = acc;
    else        g_v[c*FE + (j - 64)] = acc;
}

// ------------------------- k7a: q projection --------------------------------
__global__ __launch_bounds__(256) void k7a_q(const float* __restrict__ qw,
                                             const float* __restrict__ qb) {
    __shared__ float4 qw_s[FE*16];
    __shared__ float qb_s[FE];
    for (int i = threadIdx.x; i < FE*16; i += 256)
        qw_s[i] = reinterpret_cast<const float4*>(qw)[i];
    if (threadIdx.x < FE) qb_s[threadIdx.x] = qb[threadIdx.x];
    __syncthreads();

    int idx = blockIdx.x*256 + threadIdx.x;
    int n = idx >> 2, j0 = (idx & 3) * 16;
    float fr[FE];
    const float4* frp = reinterpret_cast<const float4*>(g_fea + n*FE);
#pragma unroll
    for (int f4 = 0; f4 < 16; f4++) {
        float4 v = frp[f4];
        fr[f4*4] = v.x; fr[f4*4+1] = v.y; fr[f4*4+2] = v.z; fr[f4*4+3] = v.w;
    }
    for (int jj = 0; jj < 16; jj++) {
        int j = j0 + jj;
        float acc = qb_s[j];
        const float4* wr = qw_s + j*16;
#pragma unroll
        for (int f4 = 0; f4 < 16; f4++) {
            float4 w = wr[f4];
            acc += fr[f4*4]*w.x + fr[f4*4+1]*w.y + fr[f4*4+2]*w.z + fr[f4*4+3]*w.w;
        }
        g_q[n*FE + j] = acc;
    }
}

// ------------------------- k7b1: attention logits ---------------------------
__global__ __launch_bounds__(256) void k7b1_al() {
    __shared__ float4 k_s[KK*16];
    for (int i = threadIdx.x; i < KK*16; i += 256)
        k_s[i] = reinterpret_cast<const float4*>(g_k)[i];
    __syncthreads();

    int idx = blockIdx.x*256 + threadIdx.x;
    int n = idx >> 2, c0 = (idx & 3) * 16;
    float qr[FE];
    const float4* qp = reinterpret_cast<const float4*>(g_q + n*FE);
#pragma unroll
    for (int f4 = 0; f4 < 16; f4++) {
        float4 v = qp[f4];
        qr[f4*4] = v.x; qr[f4*4+1] = v.y; qr[f4*4+2] = v.z; qr[f4*4+3] = v.w;
    }
    for (int cc = 0; cc < 16; cc++) {
        int c = c0 + cc;
        const float4* kr = k_s + c*16;
        float l = 0.f;
#pragma unroll
        for (int f4 = 0; f4 < 16; f4++) {
            float4 w = kr[f4];
            l += qr[f4*4]*w.x + qr[f4*4+1]*w.y + qr[f4*4+2]*w.z + qr[f4*4+3]*w.w;
        }
        g_attn[n*KK + c] = l * 0.125f;
    }
}

// ------------------------- k7b2: row softmax --------------------------------
__global__ void k7b2_sm() {                      // grid 32, block 256
    int n = blockIdx.x*256 + threadIdx.x;
    float a[KK];
    float4* ap = reinterpret_cast<float4*>(g_attn + n*KK);
    float m = -1e30f;
#pragma unroll
    for (int i = 0; i < 16; i++) {
        float4 v = ap[i];
        a[i*4] = v.x; a[i*4+1] = v.y; a[i*4+2] = v.z; a[i*4+3] = v.w;
        m = fmaxf(m, fmaxf(fmaxf(v.x, v.y), fmaxf(v.z, v.w)));
    }
    float s = 0.f;
#pragma unroll
    for (int c = 0; c < KK; c++) { a[c] = __expf(a[c] - m); s += a[c]; }
    float si = 1.f / s;
#pragma unroll
    for (int i = 0; i < 16; i++)
        ap[i] = make_float4(a[i*4]*si, a[i*4+1]*si, a[i*4+2]*si, a[i*4+3]*si);
}

// ------------------------- k7c: out = attn @ v ------------------------------
__global__ __launch_bounds__(256) void k7c_out() {
    __shared__ float4 v_s[KK*16];
    for (int i = threadIdx.x; i < KK*16; i += 256)
        v_s[i] = reinterpret_cast<const float4*>(g_v)[i];
    __syncthreads();

    int idx = blockIdx.x*256 + threadIdx.x;
    int n = idx >> 2, f0 = (idx & 3) * 16;
    float a[KK];
    const float4* ap = reinterpret_cast<const float4*>(g_attn + n*KK);
#pragma unroll
    for (int i = 0; i < 16; i++) {
        float4 v = ap[i];
        a[i*4] = v.x; a[i*4+1] = v.y; a[i*4+2] = v.z; a[i*4+3] = v.w;
    }
    float acc[16];
#pragma unroll
    for (int k = 0; k < 16; k++) acc[k] = 0.f;
    for (int c = 0; c < KK; c++) {
        float ac = a[c];
        const float4* vr = v_s + c*16 + (f0 >> 2);
#pragma unroll
        for (int k = 0; k < 4; k++) {
            float4 v = vr[k];
            acc[k*4]   += ac*v.x; acc[k*4+1] += ac*v.y;
            acc[k*4+2] += ac*v.z; acc[k*4+3] += ac*v.w;
        }
    }
    float4* op = reinterpret_cast<float4*>(g_out + n*FE + f0);
#pragma unroll
    for (int k = 0; k < 4; k++)
        op[k] = make_float4(acc[k*4], acc[k*4+1], acc[k*4+2], acc[k*4+3]);
}

// ------------------------- k8: scatter tokens to volume ---------------------
__global__ void k8_scatter() {
    int idx = blockIdx.x*256 + threadIdx.x;
    int n = idx >> 6, f = idx & 63;
    int xb = n & 31, yb = (n >> 5) & 31, zb = n >> 10;
    int px = f & 3, py = (f >> 2) & 3, pz = f >> 4;
    int p = ((zb*4 + pz)*HH + (yb*4 + py))*WW + (xb*4 + px);
    g_o1[p] = g_out[idx];
}

// ------------------------- k9: upc conv + bias + residual (staged) ----------
// Block 128 threads / 256 voxels; thread owns 2 voxels (o1 window in regs as
// broadcast f32x2 pairs). x/out staged via shared in 8-channel slabs so all
// global traffic is sector-perfect. 1 weight LDS feeds 2 FFMA2.
#define K9_NV 256
__global__ __launch_bounds__(128) void k9_upc(const float* __restrict__ x,
                                              const float* __restrict__ uw,
                                              const float* __restrict__ ub,
                                              float* __restrict__ out) {
    __shared__ u64 w2[48*27];
    __shared__ float2 b2[48];
    __shared__ float xs[8][K9_NV + 4];
    __shared__ float os[8][K9_NV + 4];
    int tid = threadIdx.x;
    for (int i = tid; i < 48*27; i += 128) {
        int q = i / 27, t = i % 27;
        w2[i] = pk2(uw[(2*q)*27 + t], uw[(2*q+1)*27 + t]);
    }
    if (tid < 48) b2[tid] = make_float2(ub[2*tid], ub[2*tid+1]);

    int vbase = blockIdx.x * K9_NV;
    int pa = vbase + tid, pb = vbase + 128 + tid;

    u64 oa[27], ob[27];
    {
        int za = pa >> 14, ya = (pa >> 7) & 127, xa = pa & 127;
        int zb = pb >> 14, yb = (pb >> 7) & 127, xb = pb & 127;
#pragma unroll
        for (int kz = 0; kz < 3; kz++)
#pragma unroll
        for (int ky = 0; ky < 3; ky++)
#pragma unroll
        for (int kx = 0; kx < 3; kx++) {
            int t = kz*9 + ky*3 + kx;
            int zz = za + kz - 1, yy = ya + ky - 1, xc = xa + kx - 1;
            float v = 0.f;
            if ((unsigned)zz < DD && (unsigned)yy < HH && (unsigned)xc < WW)
                v = g_o1[(zz*HH + yy)*WW + xc];
            oa[t] = pk2(v, v);
            zz = zb + kz - 1; yy = yb + ky - 1; xc = xb + kx - 1;
            v = 0.f;
            if ((unsigned)zz < DD && (unsigned)yy < HH && (unsigned)xc < WW)
                v = g_o1[(zz*HH + yy)*WW + xc];
            ob[t] = pk2(v, v);
        }
    }

    for (int cb = 0; cb < CC; cb += 8) {
        __syncthreads();                          // xs/os safe to reuse
#pragma unroll
        for (int it = 0; it < 4; it++) {          // stage x slab, coalesced
            int e = it*128 + tid;
            int v = e >> 1, slot = e & 1;
            float4 val = *reinterpret_cast<const float4*>(
                x + (size_t)(vbase + v)*CC + cb + slot*4);
            xs[slot*4+0][v] = val.x; xs[slot*4+1][v] = val.y;
            xs[slot*4+2][v] = val.z; xs[slot*4+3][v] = val.w;
        }
        __syncthreads();
#pragma unroll
        for (int q = 0; q < 4; q++) {             // channel pair cb+2q, cb+2q+1
            float2 bb = b2[cb/2 + q];
            u64 acc_a = pk2(xs[2*q][tid]     + bb.x, xs[2*q+1][tid]     + bb.y);
            u64 acc_b = pk2(xs[2*q][128+tid] + bb.x, xs[2*q+1][128+tid] + bb.y);
            const u64* wr = w2 + (cb/2 + q)*27;
#pragma unroll
            for (int t = 0; t < 27; t++) {
                u64 w = wr[t];
                acc_a = ffma2(oa[t], w, acc_a);
                acc_b = ffma2(ob[t], w, acc_b);
            }
            float2 ra = upk2(acc_a), rb = upk2(acc_b);
            os[2*q][tid]     = ra.x; os[2*q+1][tid]     = ra.y;
            os[2*q][128+tid] = rb.x; os[2*q+1][128+tid] = rb.y;
        }
        __syncthreads();
#pragma unroll
        for (int it = 0; it < 4; it++) {          // drain out slab, coalesced
            int e = it*128 + tid;
            int v = e >> 1, slot = e & 1;
            float4 val = make_float4(os[slot*4+0][v], os[slot*4+1][v],
                                     os[slot*4+2][v], os[slot*4+3][v]);
            *reinterpret_cast<float4*>(
                out + (size_t)(vbase + v)*CC + cb + slot*4) = val;
        }
    }
}

// ------------------------- launch --------------------------------------------
extern "C" void kernel_launch(void* const* d_in, const int* in_sizes, int n_in,
                              void* d_out, int out_size) {
    const float* x     = (const float*)d_in[0];
    const float* cen   = (const float*)d_in[1];
    const float* dwc_w = (const float*)d_in[2];
    const float* dwc_b = (const float*)d_in[3];
    const float* upc_w = (const float*)d_in[4];
    const float* upc_b = (const float*)d_in[5];
    const float* q_w   = (const float*)d_in[6];
    const float* q_b   = (const float*)d_in[7];
    const float* kv_w  = (const float*)d_in[8];
    const float* kv_b  = (const float*)d_in[9];
    float* out = (float*)d_out;

    k0_init   <<<1, 64>>>();
    k1_dwc1   <<<NP/K1_NV, 128>>>(x, dwc_w);
    k2_gather <<<NP/256,   256>>>(dwc_b);
    k3_inv    <<<1, 64>>>();
    k4a_norm  <<<(NT*FE/4)/256, 256>>>();
    k4b_logits<<<(NT*4)/256, 256>>>(cen);
    k4c_colsum<<<KK, 256>>>();
    k5_newc   <<<KK, 256>>>();
    k6_kv     <<<KK, 128>>>(kv_w, kv_b);
    k7a_q     <<<(NT*4)/256, 256>>>(q_w, q_b);
    k7b1_al   <<<(NT*4)/256, 256>>>();
    k7b2_sm   <<<NT/256, 256>>>();
    k7c_out   <<<(NT*4)/256, 256>>>();
    k8_scatter<<<NP/256, 256>>>();
    k9_upc    <<<NP/K9_NV, 128>>>(x, upc_w, upc_b, out);
}

// round 6
// speedup vs baseline: 1.6482x; 1.0996x over previous
#include <cuda_runtime.h>
#include <cuda_bf16.h>
#include <math.h>

// ---------------------------------------------------------------------------
// ClusterAttn: b=1, D=32, H=128, W=128, C=96, P=4, FEAD=64, K=64
// 7-kernel pipeline:
//  k1   : dwc stage1  y_t[p] = dot_c(x[p,:], w[:,t]) -> bf16 maps (+init ssq/colsum)
//  k2   : 27-tap gather -> fea (raw) + column sum-of-squares (atomics)
//  k4b  : soft-assign logits with inv-scaled centroids, exp -> g_expl + colsum
//  k5   : new_centroids (normalized) + kv projection -> g_k, g_v
//  kM   : M = 0.125 * (k @ q_w) * inv,  d = 0.125 * (k @ q_b)   [64x64 fold]
//  kAttn: logits = fea.M + d -> softmax -> out = attn@v -> scatter to o1
//  k9   : upc conv (1->96) + bias + residual x (staged smem slabs)
// ---------------------------------------------------------------------------

#define DD 32
#define HH 128
#define WW 128
#define NP (DD*HH*WW)      // 524288 voxels
#define CC 96
#define NT 8192            // tokens
#define FE 64              // FEAD
#define KK 64              // clusters

// ------------------------- scratch (device globals) -------------------------
__device__ __align__(256) __nv_bfloat16 g_yb[27*NP];   // 28.3 MB
__device__ __align__(256) float g_fea[NT*FE];          // raw (un-normalized)
__device__ __align__(256) float g_expl[NT*KK];
__device__ __align__(256) float g_o1[NP];
__device__ __align__(256) float g_ssq[FE];
__device__ __align__(256) float g_colsum[KK];
__device__ __align__(256) float g_k[KK*FE];
__device__ __align__(256) float g_v[KK*FE];
__device__ __align__(256) float g_M[KK*FE];
__device__ __align__(256) float g_d[KK];

// ------------------------- f32x2 packed helpers -----------------------------
using u64 = unsigned long long;
__device__ __forceinline__ u64 pk2(float a, float b) {
    u64 r; asm("mov.b64 %0,{%1,%2};" : "=l"(r) : "f"(a), "f"(b)); return r;
}
__device__ __forceinline__ float2 upk2(u64 v) {
    float2 r; asm("mov.b64 {%0,%1},%2;" : "=f"(r.x), "=f"(r.y) : "l"(v)); return r;
}
__device__ __forceinline__ u64 ffma2(u64 a, u64 b, u64 c) {
    u64 d; asm("fma.rn.f32x2 %0,%1,%2,%3;" : "=l"(d) : "l"(a), "l"(b), "l"(c)); return d;
}

// ------------------------- k1: dwc stage1  Y[NP,27] = X[NP,96] @ W[96,27] ----
// Block 128 threads / 512 voxels. x staged via shared (coalesced), 4 voxels
// per thread so each broadcast weight LDS feeds 2 FFMA2. Output bf16.
#define K1_NV 512
__global__ __launch_bounds__(128) void k1_dwc1(const float* __restrict__ x,
                                               const float* __restrict__ dwc_w) {
    __shared__ u64   w2[CC*27];          // (w,w) pairs
    __shared__ float xs[8][K1_NV + 4];
    int tid = threadIdx.x;
    for (int i = tid; i < CC*27; i += 128) { float v = dwc_w[i]; w2[i] = pk2(v, v); }
    if (blockIdx.x == 0 && tid < FE) { g_ssq[tid] = 0.f; g_colsum[tid] = 0.f; }

    int vbase = blockIdx.x * K1_NV;
    u64 acc0[27], acc1[27];
#pragma unroll
    for (int t = 0; t < 27; t++) { acc0[t] = 0ull; acc1[t] = 0ull; }

    for (int cb = 0; cb < CC; cb += 8) {
        __syncthreads();
#pragma unroll
        for (int it = 0; it < 8; it++) {       // stage 512 vox x 8 ch, coalesced
            int e = it*128 + tid;
            int v = e >> 1, slot = e & 1;
            float4 val = *reinterpret_cast<const float4*>(
                x + (size_t)(vbase + v)*CC + cb + slot*4);
            xs[slot*4+0][v] = val.x;
            xs[slot*4+1][v] = val.y;
            xs[slot*4+2][v] = val.z;
            xs[slot*4+3][v] = val.w;
        }
        __syncthreads();
        int vq = tid*4;
#pragma unroll
        for (int cq = 0; cq < 2; cq++) {
            u64 p[4], r[4];
#pragma unroll
            for (int j = 0; j < 4; j++) {
                float4 xv = *reinterpret_cast<const float4*>(&xs[cq*4+j][vq]);
                p[j] = pk2(xv.x, xv.y);
                r[j] = pk2(xv.z, xv.w);
            }
            const u64* wc = w2 + (cb + cq*4)*27;
#pragma unroll
            for (int t = 0; t < 27; t++) {
                u64 wa = wc[t], wb = wc[27+t], wv = wc[54+t], wd = wc[81+t];
                acc0[t] = ffma2(p[0], wa, acc0[t]); acc1[t] = ffma2(r[0], wa, acc1[t]);
                acc0[t] = ffma2(p[1], wb, acc0[t]); acc1[t] = ffma2(r[1], wb, acc1[t]);
                acc0[t] = ffma2(p[2], wv, acc0[t]); acc1[t] = ffma2(r[2], wv, acc1[t]);
                acc0[t] = ffma2(p[3], wd, acc0[t]); acc1[t] = ffma2(r[3], wd, acc1[t]);
            }
        }
    }
    int gq = vbase + tid*4;
#pragma unroll
    for (int t = 0; t < 27; t++) {
        float2 a = upk2(acc0[t]), b = upk2(acc1[t]);
        __nv_bfloat162 h0 = __floats2bfloat162_rn(a.x, a.y);
        __nv_bfloat162 h1 = __floats2bfloat162_rn(b.x, b.y);
        uint2 st;
        st.x = *reinterpret_cast<unsigned int*>(&h0);
        st.y = *reinterpret_cast<unsigned int*>(&h1);
        *reinterpret_cast<uint2*>(
            reinterpret_cast<char*>(g_yb) + ((size_t)t*NP + gq)*2) = st;
    }
}

// ------------------------- k2: gather + fea (raw) + ssq ----------------------
__global__ __launch_bounds__(256) void k2_gather(const float* __restrict__ dwc_b) {
    __shared__ float ssq_s[FE];
    int tid = threadIdx.x;
    if (tid < FE) ssq_s[tid] = 0.f;
    __syncthreads();

    int p = blockIdx.x*256 + tid;
    int z = p >> 14, y = (p >> 7) & 127, xx = p & 127;

    float v = dwc_b[0];
#pragma unroll
    for (int kz = 0; kz < 3; kz++) {
        int zz = z + kz - 1; if ((unsigned)zz >= DD) continue;
#pragma unroll
        for (int ky = 0; ky < 3; ky++) {
            int yy = y + ky - 1; if ((unsigned)yy >= HH) continue;
#pragma unroll
            for (int kx = 0; kx < 3; kx++) {
                int xc = xx + kx - 1; if ((unsigned)xc >= WW) continue;
                int t = kz*9 + ky*3 + kx;
                v += __bfloat162float(g_yb[(size_t)t*NP + (zz*HH + yy)*WW + xc]);
            }
        }
    }
    int n = ((z >> 2) << 10) | ((y >> 2) << 5) | (xx >> 2);
    int f = ((z & 3) << 4) | ((y & 3) << 2) | (xx & 3);
    g_fea[n*FE + f] = v;
    atomicAdd(&ssq_s[f], v*v);
    __syncthreads();
    if (tid < FE) atomicAdd(&g_ssq[tid], ssq_s[tid]);
}

// ------------------------- k4b: soft-assign logits + exp + colsum -----------
// Normalization folded into centroids: logit = sum_i fea_raw_i * (cen_ci*inv_i)
__global__ __launch_bounds__(256) void k4b_logits(const float* __restrict__ cen) {
    __shared__ float4 cen_s[KK*16];
    __shared__ float inv_s[FE];
    __shared__ float cs_s[KK];
    int tid = threadIdx.x;
    if (tid < FE) inv_s[tid] = 1.f / fmaxf(sqrtf(g_ssq[tid]), 1e-12f);
    if (tid < KK) cs_s[tid] = 0.f;
    __syncthreads();
    for (int i = tid; i < KK*16; i += 256) {
        float4 w = reinterpret_cast<const float4*>(cen)[i];
        int f0 = (i*4) & 63;
        w.x *= inv_s[f0]; w.y *= inv_s[f0+1]; w.z *= inv_s[f0+2]; w.w *= inv_s[f0+3];
        cen_s[i] = w;
    }
    __syncthreads();

    int idx = blockIdx.x*256 + tid;              // (n, c-quarter)
    int n = idx >> 2, c0 = (idx & 3) * 16;
    float fr[FE];
    const float4* frp = reinterpret_cast<const float4*>(g_fea + n*FE);
#pragma unroll
    for (int f4 = 0; f4 < 16; f4++) {
        float4 v = frp[f4];
        fr[f4*4] = v.x; fr[f4*4+1] = v.y; fr[f4*4+2] = v.z; fr[f4*4+3] = v.w;
    }
#pragma unroll
    for (int cc = 0; cc < 16; cc++) {
        int c = c0 + cc;
        const float4* cr = cen_s + c*16;
        float l = 0.f;
#pragma unroll
        for (int f4 = 0; f4 < 16; f4++) {
            float4 w = cr[f4];
            l += fr[f4*4]*w.x + fr[f4*4+1]*w.y + fr[f4*4+2]*w.z + fr[f4*4+3]*w.w;
        }
        float e = __expf(l);
        g_expl[n*KK + c] = e;
        atomicAdd(&cs_s[c], e);
    }
    __syncthreads();
    if (tid < KK) atomicAdd(&g_colsum[tid], cs_s[tid]);
}

// ------------------------- k5: normalized new_centroids + kv ----------------
__global__ __launch_bounds__(256) void k5_newc_kv(const float* __restrict__ kv_w,
                                                  const float* __restrict__ kv_b) {
    int c = blockIdx.x;                          // grid 64
    int tid = threadIdx.x;
    float acc[FE];
#pragma unroll
    for (int f = 0; f < FE; f++) acc[f] = 0.f;
    for (int n = tid; n < NT; n += 256) {
        float e = g_expl[n*KK + c];
        const float4* fr = reinterpret_cast<const float4*>(g_fea + n*FE);
#pragma unroll
        for (int f4 = 0; f4 < 16; f4++) {
            float4 v = fr[f4];
            acc[f4*4]   += e*v.x; acc[f4*4+1] += e*v.y;
            acc[f4*4+2] += e*v.z; acc[f4*4+3] += e*v.w;
        }
    }
    __shared__ float red[FE];
    if (tid < FE) red[tid] = 0.f;
    __syncthreads();
    int lane = tid & 31;
#pragma unroll
    for (int f = 0; f < FE; f++) {
        float r = acc[f];
#pragma unroll
        for (int o = 16; o > 0; o >>= 1) r += __shfl_down_sync(0xffffffffu, r, o);
        if (lane == 0) atomicAdd(&red[f], r);
    }
    __syncthreads();
    __shared__ float nc_s[FE];
    if (tid < FE) {
        float inv = 1.f / fmaxf(sqrtf(g_ssq[tid]), 1e-12f);
        nc_s[tid] = red[tid] * inv / g_colsum[c];    // normalized new centroid
    }
    __syncthreads();
    if (tid < 128) {                              // kv projection, fused k6
        int j = tid;
        float a = kv_b[j];
        const float* wr = kv_w + j*FE;
#pragma unroll
        for (int f = 0; f < FE; f++) a += nc_s[f] * wr[f];
        if (j < 64) g_k[c*FE + j] = a;
        else        g_v[c*FE + (j - 64)] = a;
    }
}

// ------------------------- kM: fold q-proj into 64x64 matrix ----------------
// M[c][i] = 0.125*inv[i]*sum_j k[c][j]*q_w[j][i];  d[c] = 0.125*sum_j q_b[j]*k[c][j]
__global__ void kM_fold(const float* __restrict__ qw, const float* __restrict__ qb) {
    __shared__ float k_s[FE];
    int c = blockIdx.x, i = threadIdx.x;          // grid 64, block 64
    k_s[i] = g_k[c*FE + i];
    __syncthreads();
    float m = 0.f;
#pragma unroll 8
    for (int j = 0; j < FE; j++) m += k_s[j] * qw[j*FE + i];
    float inv = 1.f / fmaxf(sqrtf(g_ssq[i]), 1e-12f);
    g_M[c*FE + i] = 0.125f * inv * m;
    if (i == 0) {
        float dd = 0.f;
        for (int j = 0; j < FE; j++) dd += qb[j] * k_s[j];
        g_d[c] = 0.125f * dd;
    }
}

// ------------------------- kAttn: logits -> softmax -> @v -> scatter --------
__global__ __launch_bounds__(128) void kAttn() {
    __shared__ float M_s[KK*FE];                  // 16 KB
    __shared__ float v_s[KK*FE];                  // 16 KB
    __shared__ float d_s[KK];
    int tid = threadIdx.x;
    for (int i = tid; i < KK*FE; i += 128) { M_s[i] = g_M[i]; v_s[i] = g_v[i]; }
    if (tid < KK) d_s[tid] = g_d[tid];
    __syncthreads();

    int n = blockIdx.x*128 + tid;                 // token id
    float fr[FE];
    const float4* frp = reinterpret_cast<const float4*>(g_fea + n*FE);
#pragma unroll
    for (int f4 = 0; f4 < 16; f4++) {
        float4 v = frp[f4];
        fr[f4*4] = v.x; fr[f4*4+1] = v.y; fr[f4*4+2] = v.z; fr[f4*4+3] = v.w;
    }
    float a[KK];
    float mx = -1e30f;
#pragma unroll 4
    for (int c = 0; c < KK; c++) {
        const float4* mr = reinterpret_cast<const float4*>(M_s + c*FE);
        float l = d_s[c];
#pragma unroll
        for (int f4 = 0; f4 < 16; f4++) {
            float4 w = mr[f4];
            l += fr[f4*4]*w.x + fr[f4*4+1]*w.y + fr[f4*4+2]*w.z + fr[f4*4+3]*w.w;
        }
        a[c] = l;
        mx = fmaxf(mx, l);
    }
    float s = 0.f;
#pragma unroll
    for (int c = 0; c < KK; c++) { a[c] = __expf(a[c] - mx); s += a[c]; }
    float si = 1.f / s;

    float acc[FE];
#pragma unroll
    for (int f = 0; f < FE; f++) acc[f] = 0.f;
#pragma unroll 4
    for (int c = 0; c < KK; c++) {
        float ac = a[c] * si;
        const float4* vr = reinterpret_cast<const float4*>(v_s + c*FE);
#pragma unroll
        for (int f4 = 0; f4 < 16; f4++) {
            float4 v = vr[f4];
            acc[f4*4]   += ac*v.x; acc[f4*4+1] += ac*v.y;
            acc[f4*4+2] += ac*v.z; acc[f4*4+3] += ac*v.w;
        }
    }
    // scatter token cube to 1-channel volume (f = ((z&3)<<4)|((y&3)<<2)|(x&3))
    int xb = n & 31, yb = (n >> 5) & 31, zb = n >> 10;
#pragma unroll
    for (int f4 = 0; f4 < 16; f4++) {
        int pz = f4 >> 2, py = f4 & 3;
        int p = ((zb*4 + pz)*HH + (yb*4 + py))*WW + xb*4;
        *reinterpret_cast<float4*>(g_o1 + p) =
            make_float4(acc[f4*4], acc[f4*4+1], acc[f4*4+2], acc[f4*4+3]);
    }
}

// ------------------------- k9: upc conv + bias + residual (staged) ----------
#define K9_NV 256
__global__ __launch_bounds__(128) void k9_upc(const float* __restrict__ x,
                                              const float* __restrict__ uw,
                                              const float* __restrict__ ub,
                                              float* __restrict__ out) {
    __shared__ u64 w2[48*27];
    __shared__ float2 b2[48];
    __shared__ float xs[8][K9_NV + 4];
    __shared__ float os[8][K9_NV + 4];
    int tid = threadIdx.x;
    for (int i = tid; i < 48*27; i += 128) {
        int q = i / 27, t = i % 27;
        w2[i] = pk2(uw[(2*q)*27 + t], uw[(2*q+1)*27 + t]);
    }
    if (tid < 48) b2[tid] = make_float2(ub[2*tid], ub[2*tid+1]);

    int vbase = blockIdx.x * K9_NV;
    int pa = vbase + tid, pb = vbase + 128 + tid;

    u64 oa[27], ob[27];
    {
        int za = pa >> 14, ya = (pa >> 7) & 127, xa = pa & 127;
        int zb = pb >> 14, yb = (pb >> 7) & 127, xb = pb & 127;
#pragma unroll
        for (int kz = 0; kz < 3; kz++)
#pragma unroll
        for (int ky = 0; ky < 3; ky++)
#pragma unroll
        for (int kx = 0; kx < 3; kx++) {
            int t = kz*9 + ky*3 + kx;
            int zz = za + kz - 1, yy = ya + ky - 1, xc = xa + kx - 1;
            float v = 0.f;
            if ((unsigned)zz < DD && (unsigned)yy < HH && (unsigned)xc < WW)
                v = g_o1[(zz*HH + yy)*WW + xc];
            oa[t] = pk2(v, v);
            zz = zb + kz - 1; yy = yb + ky - 1; xc = xb + kx - 1;
            v = 0.f;
            if ((unsigned)zz < DD && (unsigned)yy < HH && (unsigned)xc < WW)
                v = g_o1[(zz*HH + yy)*WW + xc];
            ob[t] = pk2(v, v);
        }
    }

    for (int cb = 0; cb < CC; cb += 8) {
        __syncthreads();
#pragma unroll
        for (int it = 0; it < 4; it++) {          // stage x slab, coalesced
            int e = it*128 + tid;
            int v = e >> 1, slot = e & 1;
            float4 val = *reinterpret_cast<const float4*>(
                x + (size_t)(vbase + v)*CC + cb + slot*4);
            xs[slot*4+0][v] = val.x; xs[slot*4+1][v] = val.y;
            xs[slot*4+2][v] = val.z; xs[slot*4+3][v] = val.w;
        }
        __syncthreads();
#pragma unroll
        for (int q = 0; q < 4; q++) {             // channel pair cb+2q, cb+2q+1
            float2 bb = b2[cb/2 + q];
            u64 acc_a = pk2(xs[2*q][tid]     + bb.x, xs[2*q+1][tid]     + bb.y);
            u64 acc_b = pk2(xs[2*q][128+tid] + bb.x, xs[2*q+1][128+tid] + bb.y);
            const u64* wr = w2 + (cb/2 + q)*27;
#pragma unroll
            for (int t = 0; t < 27; t++) {
                u64 w = wr[t];
                acc_a = ffma2(oa[t], w, acc_a);
                acc_b = ffma2(ob[t], w, acc_b);
            }
            float2 ra = upk2(acc_a), rb = upk2(acc_b);
            os[2*q][tid]     = ra.x; os[2*q+1][tid]     = ra.y;
            os[2*q][128+tid] = rb.x; os[2*q+1][128+tid] = rb.y;
        }
        __syncthreads();
#pragma unroll
        for (int it = 0; it < 4; it++) {          // drain out slab, coalesced
            int e = it*128 + tid;
            int v = e >> 1, slot = e & 1;
            float4 val = make_float4(os[slot*4+0][v], os[slot*4+1][v],
                                     os[slot*4+2][v], os[slot*4+3][v]);
            *reinterpret_cast<float4*>(
                out + (size_t)(vbase + v)*CC + cb + slot*4) = val;
        }
    }
}

// ------------------------- launch --------------------------------------------
extern "C" void kernel_launch(void* const* d_in, const int* in_sizes, int n_in,
                              void* d_out, int out_size) {
    const float* x     = (const float*)d_in[0];
    const float* cen   = (const float*)d_in[1];
    const float* dwc_w = (const float*)d_in[2];
    const float* dwc_b = (const float*)d_in[3];
    const float* upc_w = (const float*)d_in[4];
    const float* upc_b = (const float*)d_in[5];
    const float* q_w   = (const float*)d_in[6];
    const float* q_b   = (const float*)d_in[7];
    const float* kv_w  = (const float*)d_in[8];
    const float* kv_b  = (const float*)d_in[9];
    float* out = (float*)d_out;

    k1_dwc1   <<<NP/K1_NV, 128>>>(x, dwc_w);
    k2_gather <<<NP/256,   256>>>(dwc_b);
    k4b_logits<<<(NT*4)/256, 256>>>(cen);
    k5_newc_kv<<<KK, 256>>>(kv_w, kv_b);
    kM_fold   <<<KK, 64>>>(q_w, q_b);
    kAttn     <<<NT/128, 128>>>();
    k9_upc    <<<NP/K9_NV, 128>>>(x, upc_w, upc_b, out);
}

// round 7
// speedup vs baseline: 1.8207x; 1.1047x over previous
#include <cuda_runtime.h>
#include <cuda_bf16.h>
#include <math.h>

// ---------------------------------------------------------------------------
// ClusterAttn: b=1, D=32, H=128, W=128, C=96, P=4, FEAD=64, K=64
// 7-kernel pipeline:
//  k1   : dwc stage1  y_t[p] = dot_c(x[p,:], w[:,t]) -> bf16 maps (+init accums)
//  k2   : 27-tap gather -> fea (raw) + column sum-of-squares (atomics)
//  k4b  : soft-assign logits with inv-scaled centroids, exp -> g_expl + colsum
//  k5a  : newcacc = E^T @ fea  (tiled 64x64x64 mini-GEMMs, 128 blocks, atomics)
//  k5b  : normalize -> kv projection -> fold M = 0.125*(k@q_w)*inv, d = 0.125*k@q_b
//  kAttn: logits = fea.M + d -> softmax -> out = attn@v -> scatter to o1
//  k9   : upc conv (1->96) + bias + residual x (staged smem slabs)
// ---------------------------------------------------------------------------

#define DD 32
#define HH 128
#define WW 128
#define NP (DD*HH*WW)      // 524288 voxels
#define CC 96
#define NT 8192            // tokens
#define FE 64              // FEAD
#define KK 64              // clusters

// ------------------------- scratch (device globals) -------------------------
__device__ __align__(256) __nv_bfloat16 g_yb[27*NP];   // 28.3 MB
__device__ __align__(256) float g_fea[NT*FE];          // raw (un-normalized)
__device__ __align__(256) float g_expl[NT*KK];
__device__ __align__(256) float g_o1[NP];
__device__ __align__(256) float g_ssq[FE];
__device__ __align__(256) float g_colsum[KK];
__device__ __align__(256) float g_newcacc[KK*FE];
__device__ __align__(256) float g_v[KK*FE];
__device__ __align__(256) float g_M[KK*FE];
__device__ __align__(256) float g_d[KK];

// ------------------------- f32x2 packed helpers -----------------------------
using u64 = unsigned long long;
__device__ __forceinline__ u64 pk2(float a, float b) {
    u64 r; asm("mov.b64 %0,{%1,%2};" : "=l"(r) : "f"(a), "f"(b)); return r;
}
__device__ __forceinline__ float2 upk2(u64 v) {
    float2 r; asm("mov.b64 {%0,%1},%2;" : "=f"(r.x), "=f"(r.y) : "l"(v)); return r;
}
__device__ __forceinline__ u64 ffma2(u64 a, u64 b, u64 c) {
    u64 d; asm("fma.rn.f32x2 %0,%1,%2,%3;" : "=l"(d) : "l"(a), "l"(b), "l"(c)); return d;
}

// ------------------------- k1: dwc stage1  Y[NP,27] = X[NP,96] @ W[96,27] ----
#define K1_NV 512
__global__ __launch_bounds__(128) void k1_dwc1(const float* __restrict__ x,
                                               const float* __restrict__ dwc_w) {
    __shared__ u64   w2[CC*27];          // (w,w) pairs
    __shared__ float xs[8][K1_NV + 4];
    int tid = threadIdx.x;
    for (int i = tid; i < CC*27; i += 128) { float v = dwc_w[i]; w2[i] = pk2(v, v); }
    if (blockIdx.x == 0) {
        if (tid < FE) { g_ssq[tid] = 0.f; g_colsum[tid] = 0.f; }
        for (int i = tid; i < KK*FE; i += 128) g_newcacc[i] = 0.f;
    }

    int vbase = blockIdx.x * K1_NV;
    u64 acc0[27], acc1[27];
#pragma unroll
    for (int t = 0; t < 27; t++) { acc0[t] = 0ull; acc1[t] = 0ull; }

    for (int cb = 0; cb < CC; cb += 8) {
        __syncthreads();
#pragma unroll
        for (int it = 0; it < 8; it++) {       // stage 512 vox x 8 ch, coalesced
            int e = it*128 + tid;
            int v = e >> 1, slot = e & 1;
            float4 val = *reinterpret_cast<const float4*>(
                x + (size_t)(vbase + v)*CC + cb + slot*4);
            xs[slot*4+0][v] = val.x;
            xs[slot*4+1][v] = val.y;
            xs[slot*4+2][v] = val.z;
            xs[slot*4+3][v] = val.w;
        }
        __syncthreads();
        int vq = tid*4;
#pragma unroll
        for (int cq = 0; cq < 2; cq++) {
            u64 p[4], r[4];
#pragma unroll
            for (int j = 0; j < 4; j++) {
                float4 xv = *reinterpret_cast<const float4*>(&xs[cq*4+j][vq]);
                p[j] = pk2(xv.x, xv.y);
                r[j] = pk2(xv.z, xv.w);
            }
            const u64* wc = w2 + (cb + cq*4)*27;
#pragma unroll
            for (int t = 0; t < 27; t++) {
                u64 wa = wc[t], wb = wc[27+t], wv = wc[54+t], wd = wc[81+t];
                acc0[t] = ffma2(p[0], wa, acc0[t]); acc1[t] = ffma2(r[0], wa, acc1[t]);
                acc0[t] = ffma2(p[1], wb, acc0[t]); acc1[t] = ffma2(r[1], wb, acc1[t]);
                acc0[t] = ffma2(p[2], wv, acc0[t]); acc1[t] = ffma2(r[2], wv, acc1[t]);
                acc0[t] = ffma2(p[3], wd, acc0[t]); acc1[t] = ffma2(r[3], wd, acc1[t]);
            }
        }
    }
    int gq = vbase + tid*4;
#pragma unroll
    for (int t = 0; t < 27; t++) {
        float2 a = upk2(acc0[t]), b = upk2(acc1[t]);
        __nv_bfloat162 h0 = __floats2bfloat162_rn(a.x, a.y);
        __nv_bfloat162 h1 = __floats2bfloat162_rn(b.x, b.y);
        uint2 st;
        st.x = *reinterpret_cast<unsigned int*>(&h0);
        st.y = *reinterpret_cast<unsigned int*>(&h1);
        *reinterpret_cast<uint2*>(
            reinterpret_cast<char*>(g_yb) + ((size_t)t*NP + gq)*2) = st;
    }
}

// ------------------------- k2: gather + fea (raw) + ssq ----------------------
__global__ __launch_bounds__(256) void k2_gather(const float* __restrict__ dwc_b) {
    __shared__ float ssq_s[FE];
    int tid = threadIdx.x;
    if (tid < FE) ssq_s[tid] = 0.f;
    __syncthreads();

    int p = blockIdx.x*256 + tid;
    int z = p >> 14, y = (p >> 7) & 127, xx = p & 127;

    float v = dwc_b[0];
#pragma unroll
    for (int kz = 0; kz < 3; kz++) {
        int zz = z + kz - 1; if ((unsigned)zz >= DD) continue;
#pragma unroll
        for (int ky = 0; ky < 3; ky++) {
            int yy = y + ky - 1; if ((unsigned)yy >= HH) continue;
#pragma unroll
            for (int kx = 0; kx < 3; kx++) {
                int xc = xx + kx - 1; if ((unsigned)xc >= WW) continue;
                int t = kz*9 + ky*3 + kx;
                v += __bfloat162float(g_yb[(size_t)t*NP + (zz*HH + yy)*WW + xc]);
            }
        }
    }
    int n = ((z >> 2) << 10) | ((y >> 2) << 5) | (xx >> 2);
    int f = ((z & 3) << 4) | ((y & 3) << 2) | (xx & 3);
    g_fea[n*FE + f] = v;
    atomicAdd(&ssq_s[f], v*v);
    __syncthreads();
    if (tid < FE) atomicAdd(&g_ssq[tid], ssq_s[tid]);
}

// ------------------------- k4b: soft-assign logits + exp + colsum -----------
__global__ __launch_bounds__(256) void k4b_logits(const float* __restrict__ cen) {
    __shared__ float4 cen_s[KK*16];
    __shared__ float inv_s[FE];
    __shared__ float cs_s[KK];
    int tid = threadIdx.x;
    if (tid < FE) inv_s[tid] = 1.f / fmaxf(sqrtf(g_ssq[tid]), 1e-12f);
    if (tid < KK) cs_s[tid] = 0.f;
    __syncthreads();
    for (int i = tid; i < KK*16; i += 256) {
        float4 w = reinterpret_cast<const float4*>(cen)[i];
        int f0 = (i*4) & 63;
        w.x *= inv_s[f0]; w.y *= inv_s[f0+1]; w.z *= inv_s[f0+2]; w.w *= inv_s[f0+3];
        cen_s[i] = w;
    }
    __syncthreads();

    int idx = blockIdx.x*256 + tid;              // (n, c-quarter)
    int n = idx >> 2, c0 = (idx & 3) * 16;
    float fr[FE];
    const float4* frp = reinterpret_cast<const float4*>(g_fea + n*FE);
#pragma unroll
    for (int f4 = 0; f4 < 16; f4++) {
        float4 v = frp[f4];
        fr[f4*4] = v.x; fr[f4*4+1] = v.y; fr[f4*4+2] = v.z; fr[f4*4+3] = v.w;
    }
#pragma unroll
    for (int cc = 0; cc < 16; cc++) {
        int c = c0 + cc;
        const float4* cr = cen_s + c*16;
        float l = 0.f;
#pragma unroll
        for (int f4 = 0; f4 < 16; f4++) {
            float4 w = cr[f4];
            l += fr[f4*4]*w.x + fr[f4*4+1]*w.y + fr[f4*4+2]*w.z + fr[f4*4+3]*w.w;
        }
        float e = __expf(l);
        g_expl[n*KK + c] = e;
        atomicAdd(&cs_s[c], e);
    }
    __syncthreads();
    if (tid < KK) atomicAdd(&g_colsum[tid], cs_s[tid]);
}

// ------------------------- k5a: newcacc = E^T @ fea (tiled GEMM) ------------
// Grid 128 blocks x 64 tokens. Register 4x4 outer-product tiles, atomics out.
__global__ __launch_bounds__(256) void k5a_gemm() {
    __shared__ float e_s[64][68];                // [token][cluster], f4-aligned pad
    __shared__ float f_s[64][68];                // [token][feature]
    int tid = threadIdx.x;
    int n0 = blockIdx.x * 64;
#pragma unroll
    for (int k = 0; k < 16; k++) {               // coalesced tile loads
        int idx = k*256 + tid;
        int r = idx >> 6, c = idx & 63;
        e_s[r][c] = g_expl[(n0 + r)*KK + c];
        f_s[r][c] = g_fea [(n0 + r)*FE + c];
    }
    __syncthreads();

    int c0 = (tid >> 4) * 4;                     // 16 cluster tiles
    int f0 = (tid & 15) * 4;                     // 16 feature tiles
    float a00=0,a01=0,a02=0,a03=0, a10=0,a11=0,a12=0,a13=0;
    float a20=0,a21=0,a22=0,a23=0, a30=0,a31=0,a32=0,a33=0;
#pragma unroll 8
    for (int n = 0; n < 64; n++) {
        float4 e4 = *reinterpret_cast<const float4*>(&e_s[n][c0]);
        float4 f4 = *reinterpret_cast<const float4*>(&f_s[n][f0]);
        a00 += e4.x*f4.x; a01 += e4.x*f4.y; a02 += e4.x*f4.z; a03 += e4.x*f4.w;
        a10 += e4.y*f4.x; a11 += e4.y*f4.y; a12 += e4.y*f4.z; a13 += e4.y*f4.w;
        a20 += e4.z*f4.x; a21 += e4.z*f4.y; a22 += e4.z*f4.z; a23 += e4.z*f4.w;
        a30 += e4.w*f4.x; a31 += e4.w*f4.y; a32 += e4.w*f4.z; a33 += e4.w*f4.w;
    }
    float* base = g_newcacc + c0*FE + f0;
    atomicAdd(base+0,        a00); atomicAdd(base+1,        a01);
    atomicAdd(base+2,        a02); atomicAdd(base+3,        a03);
    atomicAdd(base+FE+0,     a10); atomicAdd(base+FE+1,     a11);
    atomicAdd(base+FE+2,     a12); atomicAdd(base+FE+3,     a13);
    atomicAdd(base+2*FE+0,   a20); atomicAdd(base+2*FE+1,   a21);
    atomicAdd(base+2*FE+2,   a22); atomicAdd(base+2*FE+3,   a23);
    atomicAdd(base+3*FE+0,   a30); atomicAdd(base+3*FE+1,   a31);
    atomicAdd(base+3*FE+2,   a32); atomicAdd(base+3*FE+3,   a33);
}

// ------------------------- k5b: normalize + kv + M/d fold -------------------
// M[c][i] = 0.125*inv[i]*sum_j k[c][j]*q_w[j][i];  d[c] = 0.125*sum_j q_b[j]*k[c][j]
__global__ __launch_bounds__(128) void k5b_kv(const float* __restrict__ kv_w,
                                              const float* __restrict__ kv_b,
                                              const float* __restrict__ qw,
                                              const float* __restrict__ qb) {
    int c = blockIdx.x;                          // grid 64
    int tid = threadIdx.x;
    __shared__ float nc_s[FE], k_s[FE];
    if (tid < FE) {
        float inv = 1.f / fmaxf(sqrtf(g_ssq[tid]), 1e-12f);
        nc_s[tid] = g_newcacc[c*FE + tid] * inv / g_colsum[c];
    }
    __syncthreads();
    {                                            // kv projection
        float a = kv_b[tid];
        const float* wr = kv_w + tid*FE;
#pragma unroll
        for (int f = 0; f < FE; f++) a += nc_s[f] * wr[f];
        if (tid < 64) k_s[tid] = a;
        else          g_v[c*FE + (tid - 64)] = a;
    }
    __syncthreads();
    if (tid < 64) {                              // M fold
        float m = 0.f;
#pragma unroll 8
        for (int j = 0; j < FE; j++) m += k_s[j] * qw[j*FE + tid];
        float inv = 1.f / fmaxf(sqrtf(g_ssq[tid]), 1e-12f);
        g_M[c*FE + tid] = 0.125f * inv * m;
    } else if (tid == 64) {                      // d fold
        float dd = 0.f;
        for (int j = 0; j < FE; j++) dd += qb[j] * k_s[j];
        g_d[c] = 0.125f * dd;
    }
}

// ------------------------- kAttn: logits -> softmax -> @v -> scatter --------
__global__ __launch_bounds__(128) void kAttn() {
    __shared__ float M_s[KK*FE];                  // 16 KB
    __shared__ float v_s[KK*FE];                  // 16 KB
    __shared__ float d_s[KK];
    int tid = threadIdx.x;
    for (int i = tid; i < KK*FE; i += 128) { M_s[i] = g_M[i]; v_s[i] = g_v[i]; }
    if (tid < KK) d_s[tid] = g_d[tid];
    __syncthreads();

    int n = blockIdx.x*128 + tid;                 // token id
    float fr[FE];
    const float4* frp = reinterpret_cast<const float4*>(g_fea + n*FE);
#pragma unroll
    for (int f4 = 0; f4 < 16; f4++) {
        float4 v = frp[f4];
        fr[f4*4] = v.x; fr[f4*4+1] = v.y; fr[f4*4+2] = v.z; fr[f4*4+3] = v.w;
    }
    float a[KK];
    float mx = -1e30f;
#pragma unroll 4
    for (int c = 0; c < KK; c++) {
        const float4* mr = reinterpret_cast<const float4*>(M_s + c*FE);
        float l = d_s[c];
#pragma unroll
        for (int f4 = 0; f4 < 16; f4++) {
            float4 w = mr[f4];
            l += fr[f4*4]*w.x + fr[f4*4+1]*w.y + fr[f4*4+2]*w.z + fr[f4*4+3]*w.w;
        }
        a[c] = l;
        mx = fmaxf(mx, l);
    }
    float s = 0.f;
#pragma unroll
    for (int c = 0; c < KK; c++) { a[c] = __expf(a[c] - mx); s += a[c]; }
    float si = 1.f / s;

    float acc[FE];
#pragma unroll
    for (int f = 0; f < FE; f++) acc[f] = 0.f;
#pragma unroll 4
    for (int c = 0; c < KK; c++) {
        float ac = a[c] * si;
        const float4* vr = reinterpret_cast<const float4*>(v_s + c*FE);
#pragma unroll
        for (int f4 = 0; f4 < 16; f4++) {
            float4 v = vr[f4];
            acc[f4*4]   += ac*v.x; acc[f4*4+1] += ac*v.y;
            acc[f4*4+2] += ac*v.z; acc[f4*4+3] += ac*v.w;
        }
    }
    int xb = n & 31, yb = (n >> 5) & 31, zb = n >> 10;
#pragma unroll
    for (int f4 = 0; f4 < 16; f4++) {
        int pz = f4 >> 2, py = f4 & 3;
        int p = ((zb*4 + pz)*HH + (yb*4 + py))*WW + xb*4;
        *reinterpret_cast<float4*>(g_o1 + p) =
            make_float4(acc[f4*4], acc[f4*4+1], acc[f4*4+2], acc[f4*4+3]);
    }
}

// ------------------------- k9: upc conv + bias + residual (staged) ----------
#define K9_NV 256
__global__ __launch_bounds__(128) void k9_upc(const float* __restrict__ x,
                                              const float* __restrict__ uw,
                                              const float* __restrict__ ub,
                                              float* __restrict__ out) {
    __shared__ u64 w2[48*27];
    __shared__ float2 b2[48];
    __shared__ float xs[8][K9_NV + 4];
    __shared__ float os[8][K9_NV + 4];
    int tid = threadIdx.x;
    for (int i = tid; i < 48*27; i += 128) {
        int q = i / 27, t = i % 27;
        w2[i] = pk2(uw[(2*q)*27 + t], uw[(2*q+1)*27 + t]);
    }
    if (tid < 48) b2[tid] = make_float2(ub[2*tid], ub[2*tid+1]);

    int vbase = blockIdx.x * K9_NV;
    int pa = vbase + tid, pb = vbase + 128 + tid;

    u64 oa[27], ob[27];
    {
        int za = pa >> 14, ya = (pa >> 7) & 127, xa = pa & 127;
        int zb = pb >> 14, yb = (pb >> 7) & 127, xb = pb & 127;
#pragma unroll
        for (int kz = 0; kz < 3; kz++)
#pragma unroll
        for (int ky = 0; ky < 3; ky++)
#pragma unroll
        for (int kx = 0; kx < 3; kx++) {
            int t = kz*9 + ky*3 + kx;
            int zz = za + kz - 1, yy = ya + ky - 1, xc = xa + kx - 1;
            float v = 0.f;
            if ((unsigned)zz < DD && (unsigned)yy < HH && (unsigned)xc < WW)
                v = g_o1[(zz*HH + yy)*WW + xc];
            oa[t] = pk2(v, v);
            zz = zb + kz - 1; yy = yb + ky - 1; xc = xb + kx - 1;
            v = 0.f;
            if ((unsigned)zz < DD && (unsigned)yy < HH && (unsigned)xc < WW)
                v = g_o1[(zz*HH + yy)*WW + xc];
            ob[t] = pk2(v, v);
        }
    }

    for (int cb = 0; cb < CC; cb += 8) {
        __syncthreads();
#pragma unroll
        for (int it = 0; it < 4; it++) {          // stage x slab, coalesced
            int e = it*128 + tid;
            int v = e >> 1, slot = e & 1;
            float4 val = *reinterpret_cast<const float4*>(
                x + (size_t)(vbase + v)*CC + cb + slot*4);
            xs[slot*4+0][v] = val.x; xs[slot*4+1][v] = val.y;
            xs[slot*4+2][v] = val.z; xs[slot*4+3][v] = val.w;
        }
        __syncthreads();
#pragma unroll
        for (int q = 0; q < 4; q++) {             // channel pair cb+2q, cb+2q+1
            float2 bb = b2[cb/2 + q];
            u64 acc_a = pk2(xs[2*q][tid]     + bb.x, xs[2*q+1][tid]     + bb.y);
            u64 acc_b = pk2(xs[2*q][128+tid] + bb.x, xs[2*q+1][128+tid] + bb.y);
            const u64* wr = w2 + (cb/2 + q)*27;
#pragma unroll
            for (int t = 0; t < 27; t++) {
                u64 w = wr[t];
                acc_a = ffma2(oa[t], w, acc_a);
                acc_b = ffma2(ob[t], w, acc_b);
            }
            float2 ra = upk2(acc_a), rb = upk2(acc_b);
            os[2*q][tid]     = ra.x; os[2*q+1][tid]     = ra.y;
            os[2*q][128+tid] = rb.x; os[2*q+1][128+tid] = rb.y;
        }
        __syncthreads();
#pragma unroll
        for (int it = 0; it < 4; it++) {          // drain out slab, coalesced
            int e = it*128 + tid;
            int v = e >> 1, slot = e & 1;
            float4 val = make_float4(os[slot*4+0][v], os[slot*4+1][v],
                                     os[slot*4+2][v], os[slot*4+3][v]);
            *reinterpret_cast<float4*>(
                out + (size_t)(vbase + v)*CC + cb + slot*4) = val;
        }
    }
}

// ------------------------- launch --------------------------------------------
extern "C" void kernel_launch(void* const* d_in, const int* in_sizes, int n_in,
                              void* d_out, int out_size) {
    const float* x     = (const float*)d_in[0];
    const float* cen   = (const float*)d_in[1];
    const float* dwc_w = (const float*)d_in[2];
    const float* dwc_b = (const float*)d_in[3];
    const float* upc_w = (const float*)d_in[4];
    const float* upc_b = (const float*)d_in[5];
    const float* q_w   = (const float*)d_in[6];
    const float* q_b   = (const float*)d_in[7];
    const float* kv_w  = (const float*)d_in[8];
    const float* kv_b  = (const float*)d_in[9];
    float* out = (float*)d_out;

    k1_dwc1   <<<NP/K1_NV, 128>>>(x, dwc_w);
    k2_gather <<<NP/256,   256>>>(dwc_b);
    k4b_logits<<<(NT*4)/256, 256>>>(cen);
    k5a_gemm  <<<NT/64, 256>>>();
    k5b_kv    <<<KK, 128>>>(kv_w, kv_b, q_w, q_b);
    kAttn     <<<NT/128, 128>>>();
    k9_upc    <<<NP/K9_NV, 128>>>(x, upc_w, upc_b, out);
}